// round 11
// baseline (speedup 1.0000x reference)
#include <cuda_runtime.h>
#include <cuda_fp16.h>
#include <math.h>
#include <stdint.h>

#define NE      8
#define HIDDEN  2048
#define INTER   768
#define O2      (2*INTER)     // 1536
#define NROT    4
#define TOKENS  4096
#define NASSIGN (TOKENS*2)    // 8192
#define CAP     NASSIGN
#define QMAXF   15.0f
#define TPE     12            // max m-tiles per expert (cap 1536 rows)

// ---------------- scratch (device globals; no allocation allowed) ----------------
__device__ __half g_gup[NE*O2*HIDDEN];       // quantized gate_up weights, ROTATED basis
__device__ __half g_dwn[NE*HIDDEN*INTER];    // quantized down weights, ROTATED basis
__device__ __half g_h[TOKENS*HIDDEN];        // rotated hidden states (fp16)
__device__ __half g_i[NASSIGN*INTER];        // inter activations (fp16)
__device__ int    g_cnt[NE];
__device__ int    g_perm[NE*CAP];
__device__ float  g_cgu[NROT*HIDDEN/2], g_sgu[NROT*HIDDEN/2];
__device__ float  g_cdn[NROT*INTER/2],  g_sdn[NROT*INTER/2];

__device__ __forceinline__ uint32_t smem_u32(const void* p) {
    uint32_t a;
    asm("{ .reg .u64 t; cvta.to.shared.u64 t, %1; cvt.u32.u64 %0, t; }" : "=r"(a) : "l"(p));
    return a;
}

// ---------------- trig tables (double; fast-math immune) + zero counters ----------
__global__ void k_trig(const float* __restrict__ ga, const float* __restrict__ da) {
    int i = blockIdx.x*blockDim.x + threadIdx.x;
    if (i < NE) g_cnt[i] = 0;
    if (i < NROT*HIDDEN/2) {
        double a = (double)ga[i];
        g_cgu[i] = (float)cos(a);
        g_sgu[i] = (float)sin(a);
    }
    if (i < NROT*INTER/2) {
        double a = (double)da[i];
        g_cdn[i] = (float)cos(a);
        g_sdn[i] = (float)sin(a);
    }
}

// ---------------- warp-level group rotation (forward) ----------------
template<int IN>
__device__ __forceinline__ void warp_rot_fwd(float* w, int lane,
                                             const int* __restrict__ prs,
                                             const float* __restrict__ ctab,
                                             const float* __restrict__ stab) {
    #pragma unroll
    for (int r = 0; r < NROT; r++) {
        const int*   pr = prs + r*IN;
        const float* cr = ctab + r*(IN/2);
        const float* sr = stab + r*(IN/2);
        int4 pp = *(const int4*)(pr + lane*4);
        float c0 = cr[2*lane],   s0 = sr[2*lane];
        float c1 = cr[2*lane+1], s1 = sr[2*lane+1];
        float wi = w[pp.x], wj = w[pp.y];
        w[pp.x] = __fsub_rn(__fmul_rn(c0, wi), __fmul_rn(s0, wj));
        w[pp.y] = __fadd_rn(__fmul_rn(s0, wi), __fmul_rn(c0, wj));
        float wi2 = w[pp.z], wj2 = w[pp.w];
        w[pp.z] = __fsub_rn(__fmul_rn(c1, wi2), __fmul_rn(s1, wj2));
        w[pp.w] = __fadd_rn(__fmul_rn(s1, wi2), __fmul_rn(c1, wj2));
        __syncwarp();
    }
}

// ---------------- weight prep: scale -> rotate -> fake-quant -> fp16 (rotated) ----
template<int IN, bool GU>
__global__ __launch_bounds__(256) void k_prep(const float* __restrict__ W,
                                              const int*   __restrict__ pairs,
                                              const float* __restrict__ ch) {
    constexpr int NG = IN/128;
    constexpr int ROWS = GU ? NE*O2 : NE*HIDDEN;
    __shared__ float sw[8][128];
    const int wid = threadIdx.x >> 5, lane = threadIdx.x & 31;
    const int gid = blockIdx.x*8 + wid;
    if (gid >= ROWS*NG) return;
    const int row = gid / NG, g = gid % NG;

    const float* src = W + (size_t)row*IN + g*128;
    const float* chp = ch + g*128;
    const float* ctab = (GU ? g_cgu : g_cdn) + g*64;
    const float* stab = (GU ? g_sgu : g_sdn) + g*64;
    const int*   prs  = pairs + g*128;
    float* w = sw[wid];

    float4 v  = *(const float4*)(src + lane*4);
    float4 cv = *(const float4*)(chp + lane*4);
    w[lane*4+0] = __fmul_rn(v.x, cv.x);
    w[lane*4+1] = __fmul_rn(v.y, cv.y);
    w[lane*4+2] = __fmul_rn(v.z, cv.z);
    w[lane*4+3] = __fmul_rn(v.w, cv.w);
    __syncwarp();

    warp_rot_fwd<IN>(w, lane, prs, ctab, stab);

    float a0 = w[lane*4+0], a1 = w[lane*4+1], a2 = w[lane*4+2], a3 = w[lane*4+3];
    float mx = fmaxf(fmaxf(a0, a1), fmaxf(a2, a3));
    float mn = fminf(fminf(a0, a1), fminf(a2, a3));
    #pragma unroll
    for (int o = 16; o; o >>= 1) {
        mx = fmaxf(mx, __shfl_xor_sync(0xffffffffu, mx, o));
        mn = fminf(mn, __shfl_xor_sync(0xffffffffu, mn, o));
    }
    float d  = fmaxf(__fsub_rn(mx, mn), 1e-5f);
    float sc = __fdiv_rn(d, QMAXF);
    float z  = rintf(__fdiv_rn(__fmul_rn(mn, -1.0f), sc));

    __half h[4];
    float av[4] = {a0, a1, a2, a3};
    #pragma unroll
    for (int k = 0; k < 4; k++) {
        float q = __fadd_rn(rintf(__fdiv_rn(av[k], sc)), z);
        q = fminf(fmaxf(q, 0.0f), QMAXF);
        h[k] = __float2half_rn(__fmul_rn(__fsub_rn(q, z), sc));
    }
    __half* out = (GU ? g_gup : g_dwn) + (size_t)row*IN + g*128 + lane*4;
    *(__half2*)(out)     = __halves2half2(h[0], h[1]);
    *(__half2*)(out + 2) = __halves2half2(h[2], h[3]);
}

// ---------------- hidden: x' = R_gu(x / ch_gu) -> fp16; zero out; + routing -------
__global__ __launch_bounds__(256) void k_hrot(const float* __restrict__ hs,
                                              const int*   __restrict__ pairs,
                                              const float* __restrict__ ch,
                                              const int*   __restrict__ topk,
                                              float* __restrict__ out) {
    constexpr int IN = HIDDEN, NG = IN/128;
    __shared__ float sw[8][128];
    const int tid = threadIdx.x;
    const int wid = tid >> 5, lane = tid & 31;

    int rid = blockIdx.x*256 + tid;
    if (rid < NASSIGN) {
        int e = topk[rid];
        int slot = atomicAdd(&g_cnt[e], 1);
        g_perm[e*CAP + slot] = rid;
    }

    const int gid = blockIdx.x*8 + wid;
    if (gid >= TOKENS*NG) return;
    const int row = gid / NG, g = gid % NG;

    const float* src = hs + (size_t)row*IN + g*128;
    const float* chp = ch + g*128;
    float* w = sw[wid];

    float4 v  = *(const float4*)(src + lane*4);
    float4 cv = *(const float4*)(chp + lane*4);
    w[lane*4+0] = __fdiv_rn(v.x, cv.x);
    w[lane*4+1] = __fdiv_rn(v.y, cv.y);
    w[lane*4+2] = __fdiv_rn(v.z, cv.z);
    w[lane*4+3] = __fdiv_rn(v.w, cv.w);
    __syncwarp();

    warp_rot_fwd<IN>(w, lane, pairs + g*128, g_cgu + g*64, g_sgu + g*64);

    __half* o = g_h + (size_t)row*IN + g*128 + lane*4;
    *(__half2*)(o)     = __floats2half2_rn(w[lane*4+0], w[lane*4+1]);
    *(__half2*)(o + 2) = __floats2half2_rn(w[lane*4+2], w[lane*4+3]);
    *(float4*)(out + (size_t)row*IN + g*128 + lane*4) = make_float4(0.f, 0.f, 0.f, 0.f);
}

// ---------------- inter: i' = R_dn(inter / ch_dn), in place on g_i ----------------
__global__ __launch_bounds__(256) void k_irot(const int*   __restrict__ pairs,
                                              const float* __restrict__ ch) {
    constexpr int IN = INTER, NG = IN/128;
    __shared__ float sw[8][128];
    const int wid = threadIdx.x >> 5, lane = threadIdx.x & 31;
    const int gid = blockIdx.x*8 + wid;
    if (gid >= NASSIGN*NG) return;
    const int row = gid / NG, g = gid % NG;

    __half* base = g_i + (size_t)row*IN + g*128 + lane*4;
    const float* chp = ch + g*128 + lane*4;
    float* w = sw[wid];

    __half2 v01 = *(__half2*)(base);
    __half2 v23 = *(__half2*)(base + 2);
    w[lane*4+0] = __fdiv_rn(__half2float(__low2half(v01)),  chp[0]);
    w[lane*4+1] = __fdiv_rn(__half2float(__high2half(v01)), chp[1]);
    w[lane*4+2] = __fdiv_rn(__half2float(__low2half(v23)),  chp[2]);
    w[lane*4+3] = __fdiv_rn(__half2float(__high2half(v23)), chp[3]);
    __syncwarp();

    warp_rot_fwd<IN>(w, lane, pairs + g*128, g_cdn + g*64, g_sdn + g*64);

    *(__half2*)(base)     = __floats2half2_rn(w[lane*4+0], w[lane*4+1]);
    *(__half2*)(base + 2) = __floats2half2_rn(w[lane*4+2], w[lane*4+3]);
}

// ---------------- grouped HMMA GEMM: CTA 128x128, 4 warps (2x2), warp 64x64 -------
// 128 threads. warp_m = wid&1 (64 rows), warp_n = wid>>1 (64 cols).
// MODE 0 (fused silu): N=128 = 64 gate + 64 up cols of inter block y*64.
// MODE 1 (fused combine): N=128 output cols at y*128.
#define PAD 40                       // halves per smem row (80B)
#define A_ROWS 128
#define STAGE_H (256*PAD)            // (128 A + 128 B) rows per stage
#define GEMM_DSMEM (3*STAGE_H*2)     // 61440 B

template<int KD, int MODE>
__global__ __launch_bounds__(128, 2) void k_gemm(const float* __restrict__ topw,
                                                 float* __restrict__ out) {
    const int e  = blockIdx.x / TPE;
    const int m0 = (blockIdx.x % TPE) * 128;
    if (m0 >= g_cnt[e]) return;
    const int y  = blockIdx.y;
    constexpr int NST = KD / 32;

    extern __shared__ __align__(16) __half dsm[];
    __shared__ int s_arow[128];

    const int tid  = threadIdx.x;
    const int wid  = tid >> 5, lane = tid & 31;

    {
        int m = m0 + tid;
        s_arow[tid] = (m < g_cnt[e]) ? g_perm[e*CAP + m] : -1;
    }
    __syncthreads();

    const __half* Ag = MODE ? g_i : g_h;
    const __half* Bg = (MODE ? g_dwn : g_gup) + (size_t)e*(MODE?HIDDEN:O2)*KD;

    // cp.async plan per stage: A 128 rows x 4 chunks = 512 ops, B same; 4+4 per thread
    const __half* srcA[4]; uint32_t dstA[4]; uint32_t szA[4];
    const __half* srcB[4]; uint32_t dstB[4];
    {
        int r = tid;                       // one row per thread
        int a = s_arow[r];
        int arowg = MODE ? a : (a >> 1);
        int brow;
        if (MODE) brow = y*128 + r;
        else      brow = (r < 64) ? (y*64 + r) : (INTER + y*64 + (r - 64));
        #pragma unroll
        for (int j = 0; j < 4; j++) {
            srcA[j] = (a >= 0) ? Ag + (size_t)arowg*KD + j*8 : Ag;
            szA[j]  = (a >= 0) ? 16u : 0u;
            dstA[j] = (uint32_t)((r*PAD + j*8) * 2);
            srcB[j] = Bg + (size_t)brow*KD + j*8;
            dstB[j] = (uint32_t)(((A_ROWS + r)*PAD + j*8) * 2);
        }
    }
    uint32_t sB[3];
    #pragma unroll
    for (int st = 0; st < 3; st++) sB[st] = smem_u32(dsm + st*STAGE_H);

    float acc[4][8][4];
    #pragma unroll
    for (int i = 0; i < 4; i++)
        #pragma unroll
        for (int j = 0; j < 8; j++)
            #pragma unroll
            for (int q = 0; q < 4; q++) acc[i][j][q] = 0.0f;

    const int mBase = (wid & 1) * 64;
    const int nBase = (wid >> 1) * 64;
    uint32_t aoff[4], boff[8];
    #pragma unroll
    for (int mi = 0; mi < 4; mi++) {
        int r = mBase + mi*16 + (lane & 15);
        int kk = (lane >> 4) * 8;
        aoff[mi] = (uint32_t)((r*PAD + kk) * 2);
    }
    #pragma unroll
    for (int ni = 0; ni < 8; ni++) {
        int r = A_ROWS + nBase + ni*8 + (lane & 7);
        int kk = ((lane >> 3) & 1) * 8;
        boff[ni] = (uint32_t)((r*PAD + kk) * 2);
    }

    #define PREFETCH(st) do {                                                  \
        const int k0_ = (st) * 32;                                             \
        uint32_t bs = sB[(st) % 3];                                            \
        _Pragma("unroll")                                                      \
        for (int j = 0; j < 4; j++) {                                          \
            asm volatile("cp.async.ca.shared.global [%0], [%1], 16, %2;"       \
                :: "r"(bs + dstA[j]), "l"(srcA[j] + k0_), "r"(szA[j]));        \
            asm volatile("cp.async.ca.shared.global [%0], [%1], 16;"           \
                :: "r"(bs + dstB[j]), "l"(srcB[j] + k0_));                     \
        }                                                                      \
        asm volatile("cp.async.commit_group;");                                \
    } while (0)

    PREFETCH(0);
    PREFETCH(1);

    for (int s = 0; s < NST; s++) {
        asm volatile("cp.async.wait_group 1;");
        __syncthreads();
        if (s + 2 < NST) PREFETCH(s + 2);
        else asm volatile("cp.async.commit_group;");
        uint32_t bs = sB[s % 3];
        #pragma unroll
        for (int ks = 0; ks < 2; ks++) {
            uint32_t a[4][4], b[8][2];
            #pragma unroll
            for (int mi = 0; mi < 4; mi++)
                asm volatile("ldmatrix.sync.aligned.m8n8.x4.shared.b16 {%0,%1,%2,%3}, [%4];"
                    : "=r"(a[mi][0]), "=r"(a[mi][1]), "=r"(a[mi][2]), "=r"(a[mi][3])
                    : "r"(bs + aoff[mi] + ks*32));
            #pragma unroll
            for (int ni = 0; ni < 8; ni++)
                asm volatile("ldmatrix.sync.aligned.m8n8.x2.shared.b16 {%0,%1}, [%2];"
                    : "=r"(b[ni][0]), "=r"(b[ni][1])
                    : "r"(bs + boff[ni] + ks*32));
            #pragma unroll
            for (int mi = 0; mi < 4; mi++)
                #pragma unroll
                for (int ni = 0; ni < 8; ni++)
                    asm volatile(
                        "mma.sync.aligned.m16n8k16.row.col.f32.f16.f16.f32 "
                        "{%0,%1,%2,%3}, {%4,%5,%6,%7}, {%8,%9}, {%0,%1,%2,%3};"
                        : "+f"(acc[mi][ni][0]), "+f"(acc[mi][ni][1]),
                          "+f"(acc[mi][ni][2]), "+f"(acc[mi][ni][3])
                        : "r"(a[mi][0]), "r"(a[mi][1]), "r"(a[mi][2]), "r"(a[mi][3]),
                          "r"(b[ni][0]), "r"(b[ni][1]));
        }
    }

    const int qrow = lane >> 2, qcol = (lane & 3) * 2;

    if (MODE == 0) {
        __syncthreads();                 // all warps out of mainloop before smem reuse
        float* sg = (float*)dsm;         // 128 x 64 fp32 = 32 KB
        if (nBase == 0) {                // gate warps (wn=0): cols 0..63
            #pragma unroll
            for (int mi = 0; mi < 4; mi++) {
                int r0 = mBase + mi*16 + qrow;
                #pragma unroll
                for (int ni = 0; ni < 8; ni++) {
                    int c = ni*8 + qcol;
                    sg[r0*64 + c]     = acc[mi][ni][0];
                    sg[r0*64 + c + 1] = acc[mi][ni][1];
                    sg[(r0+8)*64 + c]     = acc[mi][ni][2];
                    sg[(r0+8)*64 + c + 1] = acc[mi][ni][3];
                }
            }
        }
        __syncthreads();
        if (nBase != 0) {                // up warps (wn=1): inter cols 0..63
            #pragma unroll
            for (int mi = 0; mi < 4; mi++) {
                int r0 = mBase + mi*16 + qrow;
                int a0 = s_arow[r0], a1 = s_arow[r0 + 8];
                #pragma unroll
                for (int ni = 0; ni < 8; ni++) {
                    int c = ni*8 + qcol;
                    if (a0 >= 0) {
                        float gA = sg[r0*64 + c], gB = sg[r0*64 + c + 1];
                        float vA = (gA / (1.0f + expf(-gA))) * acc[mi][ni][0];
                        float vB = (gB / (1.0f + expf(-gB))) * acc[mi][ni][1];
                        *(__half2*)&g_i[(size_t)a0*INTER + y*64 + c] = __floats2half2_rn(vA, vB);
                    }
                    if (a1 >= 0) {
                        float gA = sg[(r0+8)*64 + c], gB = sg[(r0+8)*64 + c + 1];
                        float vA = (gA / (1.0f + expf(-gA))) * acc[mi][ni][2];
                        float vB = (gB / (1.0f + expf(-gB))) * acc[mi][ni][3];
                        *(__half2*)&g_i[(size_t)a1*INTER + y*64 + c] = __floats2half2_rn(vA, vB);
                    }
                }
            }
        }
    } else {
        const int n0 = y * 128;
        #pragma unroll
        for (int mi = 0; mi < 4; mi++) {
            int r0 = mBase + mi*16 + qrow;
            int a0 = s_arow[r0], a1 = s_arow[r0 + 8];
            float w0 = 0.f, w1 = 0.f;
            float *O0 = nullptr, *O1 = nullptr;
            if (a0 >= 0) { w0 = topw[a0]; O0 = out + (size_t)(a0 >> 1)*HIDDEN + n0; }
            if (a1 >= 0) { w1 = topw[a1]; O1 = out + (size_t)(a1 >> 1)*HIDDEN + n0; }
            #pragma unroll
            for (int ni = 0; ni < 8; ni++) {
                int c = nBase + ni*8 + qcol;
                if (O0) {
                    atomicAdd(&O0[c],     w0 * acc[mi][ni][0]);
                    atomicAdd(&O0[c + 1], w0 * acc[mi][ni][1]);
                }
                if (O1) {
                    atomicAdd(&O1[c],     w1 * acc[mi][ni][2]);
                    atomicAdd(&O1[c + 1], w1 * acc[mi][ni][3]);
                }
            }
        }
    }
}

// ---------------- launch ----------------
extern "C" void kernel_launch(void* const* d_in, const int* in_sizes, int n_in,
                              void* d_out, int out_size) {
    const float* hidden  = (const float*)d_in[0];
    const int*   topk    = (const int*)  d_in[1];
    const float* topw    = (const float*)d_in[2];
    const float* gup_w   = (const float*)d_in[3];
    const float* dwn_w   = (const float*)d_in[4];
    const int*   gup_p   = (const int*)  d_in[5];
    const float* gup_a   = (const float*)d_in[6];
    const int*   dwn_p   = (const int*)  d_in[7];
    const float* dwn_a   = (const float*)d_in[8];
    const float* gup_ch  = (const float*)d_in[9];
    const float* dwn_ch  = (const float*)d_in[10];
    float* out = (float*)d_out;

    static int s_attr_done = 0;
    if (!s_attr_done) {
        cudaFuncSetAttribute(k_gemm<HIDDEN,0>, cudaFuncAttributeMaxDynamicSharedMemorySize, GEMM_DSMEM);
        cudaFuncSetAttribute(k_gemm<INTER, 1>, cudaFuncAttributeMaxDynamicSharedMemorySize, GEMM_DSMEM);
        s_attr_done = 1;
    }

    k_trig<<<(NROT*HIDDEN/2 + 255)/256, 256>>>(gup_a, dwn_a);                   // 1
    k_prep<HIDDEN, true ><<<(NE*O2*16 + 7)/8,    256>>>(gup_w, gup_p, gup_ch);  // 2
    k_hrot<<<(TOKENS*16 + 7)/8, 256>>>(hidden, gup_p, gup_ch, topk, out);       // 3
    k_gemm<HIDDEN, 0><<<dim3(NE*TPE, INTER/64), 128, GEMM_DSMEM>>>(topw, out);  // 4 (profiled)
    k_prep<INTER,  false><<<(NE*HIDDEN*6 + 7)/8, 256>>>(dwn_w, dwn_p, dwn_ch);  // 5
    k_irot<<<(NASSIGN*6 + 7)/8, 256>>>(dwn_p, dwn_ch);                          // 6
    k_gemm<INTER,  1><<<dim3(NE*TPE, HIDDEN/128), 128, GEMM_DSMEM>>>(topw, out);// 7
}

// round 12
// speedup vs baseline: 1.0445x; 1.0445x over previous
#include <cuda_runtime.h>
#include <cuda_fp16.h>
#include <math.h>
#include <stdint.h>

#define NE      8
#define HIDDEN  2048
#define INTER   768
#define O2      (2*INTER)     // 1536
#define NROT    4
#define TOKENS  4096
#define NASSIGN (TOKENS*2)    // 8192
#define CAP     NASSIGN
#define QMAXF   15.0f
#define TPE     12            // max m-tiles per expert (cap 1536 rows)

// ---------------- scratch (device globals; no allocation allowed) ----------------
__device__ __half g_gup[NE*O2*HIDDEN];       // quantized gate_up weights, ROTATED basis
__device__ __half g_dwn[NE*HIDDEN*INTER];    // quantized down weights, ROTATED basis
__device__ __half g_h[TOKENS*HIDDEN];        // rotated hidden states (fp16)
__device__ __half g_i[NASSIGN*INTER];        // inter activations (fp16)
__device__ int    g_cnt[NE];
__device__ int    g_perm[NE*CAP];
__device__ float  g_cgu[NROT*HIDDEN/2], g_sgu[NROT*HIDDEN/2];
__device__ float  g_cdn[NROT*INTER/2],  g_sdn[NROT*INTER/2];

__device__ __forceinline__ uint32_t smem_u32(const void* p) {
    uint32_t a;
    asm("{ .reg .u64 t; cvta.to.shared.u64 t, %1; cvt.u32.u64 %0, t; }" : "=r"(a) : "l"(p));
    return a;
}

// ---------------- trig tables (double; fast-math immune) + zero counters ----------
__global__ void k_trig(const float* __restrict__ ga, const float* __restrict__ da) {
    int i = blockIdx.x*blockDim.x + threadIdx.x;
    if (i < NE) g_cnt[i] = 0;
    if (i < NROT*HIDDEN/2) {
        double a = (double)ga[i];
        g_cgu[i] = (float)cos(a);
        g_sgu[i] = (float)sin(a);
    }
    if (i < NROT*INTER/2) {
        double a = (double)da[i];
        g_cdn[i] = (float)cos(a);
        g_sdn[i] = (float)sin(a);
    }
}

// ---------------- warp-level group rotation (forward), for activations ------------
template<int IN>
__device__ __forceinline__ void warp_rot_fwd(float* w, int lane,
                                             const int* __restrict__ prs,
                                             const float* __restrict__ ctab,
                                             const float* __restrict__ stab) {
    #pragma unroll
    for (int r = 0; r < NROT; r++) {
        const int*   pr = prs + r*IN;
        const float* cr = ctab + r*(IN/2);
        const float* sr = stab + r*(IN/2);
        int4 pp = *(const int4*)(pr + lane*4);
        float c0 = cr[2*lane],   s0 = sr[2*lane];
        float c1 = cr[2*lane+1], s1 = sr[2*lane+1];
        float wi = w[pp.x], wj = w[pp.y];
        w[pp.x] = __fsub_rn(__fmul_rn(c0, wi), __fmul_rn(s0, wj));
        w[pp.y] = __fadd_rn(__fmul_rn(s0, wi), __fmul_rn(c0, wj));
        float wi2 = w[pp.z], wj2 = w[pp.w];
        w[pp.z] = __fsub_rn(__fmul_rn(c1, wi2), __fmul_rn(s1, wj2));
        w[pp.w] = __fadd_rn(__fmul_rn(s1, wi2), __fmul_rn(c1, wj2));
        __syncwarp();
    }
}

// ---------------- weight prep v2: CTA per 128-row x 128-col group tile ------------
// SMEM tile [128 rows][129 floats]; coalesced loads, conflict-free rotation
// (stride 129 == 1 mod 32), 5 CTA barriers total; identical __f*_rn op sequence.
#define PREP_SMEM (128*129*4)   // 66048 B

template<int IN, bool GU>
__global__ __launch_bounds__(256) void k_prep2(const float* __restrict__ W,
                                               const int*   __restrict__ pairs,
                                               const float* __restrict__ ch) {
    constexpr int NG = IN/128;
    extern __shared__ float swp[];
    const int tid  = threadIdx.x;
    const int g    = blockIdx.x % NG;
    const int row0 = (blockIdx.x / NG) * 128;
    const float* ctab = GU ? g_cgu : g_cdn;
    const float* stab = GU ? g_sgu : g_sdn;

    // load + channel-scale: warp per row, lanes = float4 columns (coalesced)
    #pragma unroll
    for (int pass = 0; pass < 16; pass++) {
        int idx = tid + pass*256;          // 0..4095
        int r   = idx >> 5;                // warp-uniform row
        int c4  = (idx & 31) * 4;
        float4 v  = *(const float4*)(W  + (size_t)(row0 + r)*IN + g*128 + c4);
        float4 cv = *(const float4*)(ch + g*128 + c4);
        float* dst = swp + r*129 + c4;
        dst[0] = __fmul_rn(v.x, cv.x);
        dst[1] = __fmul_rn(v.y, cv.y);
        dst[2] = __fmul_rn(v.z, cv.z);
        dst[3] = __fmul_rn(v.w, cv.w);
    }
    __syncthreads();

    // 4 rotation rounds: 64 pairs x 128 rows = 8192 ops, warp-uniform pair
    for (int rnd = 0; rnd < NROT; rnd++) {
        const int*   pbase = pairs + rnd*IN + g*128;
        const float* cbase = ctab + rnd*(IN/2) + g*64;
        const float* sbase = stab + rnd*(IN/2) + g*64;
        #pragma unroll 4
        for (int k = 0; k < 32; k++) {
            int idx = tid + k*256;
            int p   = idx >> 7;            // warp-uniform pair index
            int r   = idx & 127;           // lanes = consecutive rows
            int2  pp = *(const int2*)(pbase + 2*p);
            float c = cbase[p], s = sbase[p];
            float wi = swp[r*129 + pp.x], wj = swp[r*129 + pp.y];
            swp[r*129 + pp.x] = __fsub_rn(__fmul_rn(c, wi), __fmul_rn(s, wj));
            swp[r*129 + pp.y] = __fadd_rn(__fmul_rn(s, wi), __fmul_rn(c, wj));
        }
        __syncthreads();
    }

    // fake-quant per row (thread-per-row; threads 128..255 idle here)
    if (tid < 128) {
        const float* wrow = swp + tid*129;
        float mx = -INFINITY, mn = INFINITY;
        #pragma unroll 8
        for (int c = 0; c < 128; c++) {
            float v = wrow[c];
            mx = fmaxf(mx, v); mn = fminf(mn, v);
        }
        float d  = fmaxf(__fsub_rn(mx, mn), 1e-5f);
        float sc = __fdiv_rn(d, QMAXF);
        float z  = rintf(__fdiv_rn(__fmul_rn(mn, -1.0f), sc));

        __half* out = (GU ? g_gup : g_dwn) + (size_t)(row0 + tid)*IN + g*128;
        #pragma unroll 8
        for (int c = 0; c < 128; c += 2) {
            float q0 = __fadd_rn(rintf(__fdiv_rn(wrow[c],   sc)), z);
            float q1 = __fadd_rn(rintf(__fdiv_rn(wrow[c+1], sc)), z);
            q0 = fminf(fmaxf(q0, 0.0f), QMAXF);
            q1 = fminf(fmaxf(q1, 0.0f), QMAXF);
            __half h0 = __float2half_rn(__fmul_rn(__fsub_rn(q0, z), sc));
            __half h1 = __float2half_rn(__fmul_rn(__fsub_rn(q1, z), sc));
            *(__half2*)(out + c) = __halves2half2(h0, h1);
        }
    }
}

// ---------------- hidden: x' = R_gu(x / ch_gu) -> fp16; zero out; + routing -------
__global__ __launch_bounds__(256) void k_hrot(const float* __restrict__ hs,
                                              const int*   __restrict__ pairs,
                                              const float* __restrict__ ch,
                                              const int*   __restrict__ topk,
                                              float* __restrict__ out) {
    constexpr int IN = HIDDEN, NG = IN/128;
    __shared__ float sw[8][128];
    const int tid = threadIdx.x;
    const int wid = tid >> 5, lane = tid & 31;

    int rid = blockIdx.x*256 + tid;
    if (rid < NASSIGN) {
        int e = topk[rid];
        int slot = atomicAdd(&g_cnt[e], 1);
        g_perm[e*CAP + slot] = rid;
    }

    const int gid = blockIdx.x*8 + wid;
    if (gid >= TOKENS*NG) return;
    const int row = gid / NG, g = gid % NG;

    const float* src = hs + (size_t)row*IN + g*128;
    const float* chp = ch + g*128;
    float* w = sw[wid];

    float4 v  = *(const float4*)(src + lane*4);
    float4 cv = *(const float4*)(chp + lane*4);
    w[lane*4+0] = __fdiv_rn(v.x, cv.x);
    w[lane*4+1] = __fdiv_rn(v.y, cv.y);
    w[lane*4+2] = __fdiv_rn(v.z, cv.z);
    w[lane*4+3] = __fdiv_rn(v.w, cv.w);
    __syncwarp();

    warp_rot_fwd<IN>(w, lane, pairs + g*128, g_cgu + g*64, g_sgu + g*64);

    __half* o = g_h + (size_t)row*IN + g*128 + lane*4;
    *(__half2*)(o)     = __floats2half2_rn(w[lane*4+0], w[lane*4+1]);
    *(__half2*)(o + 2) = __floats2half2_rn(w[lane*4+2], w[lane*4+3]);
    *(float4*)(out + (size_t)row*IN + g*128 + lane*4) = make_float4(0.f, 0.f, 0.f, 0.f);
}

// ---------------- inter: i' = R_dn(inter / ch_dn), in place on g_i ----------------
__global__ __launch_bounds__(256) void k_irot(const int*   __restrict__ pairs,
                                              const float* __restrict__ ch) {
    constexpr int IN = INTER, NG = IN/128;
    __shared__ float sw[8][128];
    const int wid = threadIdx.x >> 5, lane = threadIdx.x & 31;
    const int gid = blockIdx.x*8 + wid;
    if (gid >= NASSIGN*NG) return;
    const int row = gid / NG, g = gid % NG;

    __half* base = g_i + (size_t)row*IN + g*128 + lane*4;
    const float* chp = ch + g*128 + lane*4;
    float* w = sw[wid];

    __half2 v01 = *(__half2*)(base);
    __half2 v23 = *(__half2*)(base + 2);
    w[lane*4+0] = __fdiv_rn(__half2float(__low2half(v01)),  chp[0]);
    w[lane*4+1] = __fdiv_rn(__half2float(__high2half(v01)), chp[1]);
    w[lane*4+2] = __fdiv_rn(__half2float(__low2half(v23)),  chp[2]);
    w[lane*4+3] = __fdiv_rn(__half2float(__high2half(v23)), chp[3]);
    __syncwarp();

    warp_rot_fwd<IN>(w, lane, pairs + g*128, g_cdn + g*64, g_sdn + g*64);

    *(__half2*)(base)     = __floats2half2_rn(w[lane*4+0], w[lane*4+1]);
    *(__half2*)(base + 2) = __floats2half2_rn(w[lane*4+2], w[lane*4+3]);
}

// ---------------- grouped HMMA GEMM (R7 config: 128x128 CTA, warp 64x32) ----------
#define PAD 40                      // halves per smem row (80B)
#define BUF_H (128*PAD)             // halves per buffer
#define GEMM_DSMEM (6*BUF_H*2)      // 3 stages x (A+B) = 61440 B

template<int KD, int MODE>
__global__ __launch_bounds__(256, 2) void k_gemm(const float* __restrict__ topw,
                                                 float* __restrict__ out) {
    const int e  = blockIdx.x / TPE;
    const int m0 = (blockIdx.x % TPE) * 128;
    if (m0 >= g_cnt[e]) return;
    const int y  = blockIdx.y;
    const int n0 = y * 128;
    constexpr int NST = KD / 32;

    extern __shared__ __align__(16) __half dsm[];
    __shared__ int s_arow[128];

    const int tid  = threadIdx.x;
    const int wid  = tid >> 5, lane = tid & 31;

    if (tid < 128) {
        int m = m0 + tid;
        s_arow[tid] = (m < g_cnt[e]) ? g_perm[e*CAP + m] : -1;
    }
    __syncthreads();

    const __half* Ag = MODE ? g_i : g_h;
    const __half* Bg = (MODE ? g_dwn : g_gup) + (size_t)e*(MODE?HIDDEN:O2)*KD;

    const __half* srcA[2]; uint32_t dstA[2]; uint32_t szA[2];
    const __half* srcB[2];
    #pragma unroll
    for (int j = 0; j < 2; j++) {
        int idx = tid*2 + j;            // 0..511
        int r = idx >> 2, c16 = idx & 3;
        int a = s_arow[r];
        int arowg = MODE ? a : (a >> 1);
        srcA[j] = (a >= 0) ? Ag + (size_t)arowg*KD + c16*8 : Ag;
        szA[j]  = (a >= 0) ? 16u : 0u;
        dstA[j] = (uint32_t)((r*PAD + c16*8) * 2);
        int brow;
        if (MODE) brow = n0 + r;
        else      brow = (r < 64) ? (y*64 + r) : (INTER + y*64 + (r - 64));
        srcB[j] = Bg + (size_t)brow*KD + c16*8;
    }
    uint32_t aB[3], bB[3];
    #pragma unroll
    for (int st = 0; st < 3; st++) {
        aB[st] = smem_u32(dsm + st*BUF_H);
        bB[st] = smem_u32(dsm + 3*BUF_H + st*BUF_H);
    }

    float acc[4][4][4];
    #pragma unroll
    for (int i = 0; i < 4; i++)
        #pragma unroll
        for (int j = 0; j < 4; j++)
            #pragma unroll
            for (int q = 0; q < 4; q++) acc[i][j][q] = 0.0f;

    const int mBase = (wid & 1) * 64;
    const int nBase = (wid >> 1) * 32;
    uint32_t aoff[4], boff[4];
    #pragma unroll
    for (int mi = 0; mi < 4; mi++) {
        int r = mBase + mi*16 + (lane & 15);
        int kk = (lane >> 4) * 8;
        aoff[mi] = (uint32_t)((r*PAD + kk) * 2);
    }
    #pragma unroll
    for (int ni = 0; ni < 4; ni++) {
        int r = nBase + ni*8 + (lane & 7);
        int kk = ((lane >> 3) & 1) * 8;
        boff[ni] = (uint32_t)((r*PAD + kk) * 2);
    }

    #define PREFETCH(st) do {                                                  \
        const int k0_ = (st) * 32;                                             \
        uint32_t ab = aB[(st) % 3], bb = bB[(st) % 3];                         \
        _Pragma("unroll")                                                      \
        for (int j = 0; j < 2; j++) {                                          \
            asm volatile("cp.async.ca.shared.global [%0], [%1], 16, %2;"       \
                :: "r"(ab + dstA[j]), "l"(srcA[j] + k0_), "r"(szA[j]));        \
            asm volatile("cp.async.ca.shared.global [%0], [%1], 16;"           \
                :: "r"(bb + dstA[j]), "l"(srcB[j] + k0_));                     \
        }                                                                      \
        asm volatile("cp.async.commit_group;");                                \
    } while (0)

    PREFETCH(0);
    PREFETCH(1);

    for (int s = 0; s < NST; s++) {
        asm volatile("cp.async.wait_group 1;");
        __syncthreads();
        if (s + 2 < NST) PREFETCH(s + 2);
        else asm volatile("cp.async.commit_group;");
        uint32_t ab = aB[s % 3], bb = bB[s % 3];
        #pragma unroll
        for (int ks = 0; ks < 2; ks++) {
            uint32_t a[4][4], b[4][2];
            #pragma unroll
            for (int mi = 0; mi < 4; mi++)
                asm volatile("ldmatrix.sync.aligned.m8n8.x4.shared.b16 {%0,%1,%2,%3}, [%4];"
                    : "=r"(a[mi][0]), "=r"(a[mi][1]), "=r"(a[mi][2]), "=r"(a[mi][3])
                    : "r"(ab + aoff[mi] + ks*32));
            #pragma unroll
            for (int ni = 0; ni < 4; ni++)
                asm volatile("ldmatrix.sync.aligned.m8n8.x2.shared.b16 {%0,%1}, [%2];"
                    : "=r"(b[ni][0]), "=r"(b[ni][1])
                    : "r"(bb + boff[ni] + ks*32));
            #pragma unroll
            for (int mi = 0; mi < 4; mi++)
                #pragma unroll
                for (int ni = 0; ni < 4; ni++)
                    asm volatile(
                        "mma.sync.aligned.m16n8k16.row.col.f32.f16.f16.f32 "
                        "{%0,%1,%2,%3}, {%4,%5,%6,%7}, {%8,%9}, {%0,%1,%2,%3};"
                        : "+f"(acc[mi][ni][0]), "+f"(acc[mi][ni][1]),
                          "+f"(acc[mi][ni][2]), "+f"(acc[mi][ni][3])
                        : "r"(a[mi][0]), "r"(a[mi][1]), "r"(a[mi][2]), "r"(a[mi][3]),
                          "r"(b[ni][0]), "r"(b[ni][1]));
        }
    }

    const int qrow = lane >> 2, qcol = (lane & 3) * 2;

    if (MODE == 0) {
        __syncthreads();   // all warps done reading dsm before reuse as sg
        float* sg = (float*)dsm;   // 128 x 64 fp32 = 32 KB
        if (wid < 4) {
            #pragma unroll
            for (int mi = 0; mi < 4; mi++) {
                int r0 = mBase + mi*16 + qrow;
                #pragma unroll
                for (int ni = 0; ni < 4; ni++) {
                    int c = nBase + ni*8 + qcol;
                    sg[r0*64 + c]     = acc[mi][ni][0];
                    sg[r0*64 + c + 1] = acc[mi][ni][1];
                    sg[(r0+8)*64 + c]     = acc[mi][ni][2];
                    sg[(r0+8)*64 + c + 1] = acc[mi][ni][3];
                }
            }
        }
        __syncthreads();
        if (wid >= 4) {
            #pragma unroll
            for (int mi = 0; mi < 4; mi++) {
                int r0 = mBase + mi*16 + qrow;
                int a0 = s_arow[r0], a1 = s_arow[r0 + 8];
                #pragma unroll
                for (int ni = 0; ni < 4; ni++) {
                    int c = (nBase - 64) + ni*8 + qcol;
                    if (a0 >= 0) {
                        float gA = sg[r0*64 + c], gB = sg[r0*64 + c + 1];
                        float vA = (gA / (1.0f + expf(-gA))) * acc[mi][ni][0];
                        float vB = (gB / (1.0f + expf(-gB))) * acc[mi][ni][1];
                        *(__half2*)&g_i[(size_t)a0*INTER + y*64 + c] = __floats2half2_rn(vA, vB);
                    }
                    if (a1 >= 0) {
                        float gA = sg[(r0+8)*64 + c], gB = sg[(r0+8)*64 + c + 1];
                        float vA = (gA / (1.0f + expf(-gA))) * acc[mi][ni][2];
                        float vB = (gB / (1.0f + expf(-gB))) * acc[mi][ni][3];
                        *(__half2*)&g_i[(size_t)a1*INTER + y*64 + c] = __floats2half2_rn(vA, vB);
                    }
                }
            }
        }
    } else {
        #pragma unroll
        for (int mi = 0; mi < 4; mi++) {
            int r0 = mBase + mi*16 + qrow;
            int a0 = s_arow[r0], a1 = s_arow[r0 + 8];
            float w0 = 0.f, w1 = 0.f;
            float *O0 = nullptr, *O1 = nullptr;
            if (a0 >= 0) { w0 = topw[a0]; O0 = out + (size_t)(a0 >> 1)*HIDDEN + n0; }
            if (a1 >= 0) { w1 = topw[a1]; O1 = out + (size_t)(a1 >> 1)*HIDDEN + n0; }
            #pragma unroll
            for (int ni = 0; ni < 4; ni++) {
                int c = nBase + ni*8 + qcol;
                if (O0) {
                    atomicAdd(&O0[c],     w0 * acc[mi][ni][0]);
                    atomicAdd(&O0[c + 1], w0 * acc[mi][ni][1]);
                }
                if (O1) {
                    atomicAdd(&O1[c],     w1 * acc[mi][ni][2]);
                    atomicAdd(&O1[c + 1], w1 * acc[mi][ni][3]);
                }
            }
        }
    }
}

// ---------------- launch ----------------
extern "C" void kernel_launch(void* const* d_in, const int* in_sizes, int n_in,
                              void* d_out, int out_size) {
    const float* hidden  = (const float*)d_in[0];
    const int*   topk    = (const int*)  d_in[1];
    const float* topw    = (const float*)d_in[2];
    const float* gup_w   = (const float*)d_in[3];
    const float* dwn_w   = (const float*)d_in[4];
    const int*   gup_p   = (const int*)  d_in[5];
    const float* gup_a   = (const float*)d_in[6];
    const int*   dwn_p   = (const int*)  d_in[7];
    const float* dwn_a   = (const float*)d_in[8];
    const float* gup_ch  = (const float*)d_in[9];
    const float* dwn_ch  = (const float*)d_in[10];
    float* out = (float*)d_out;

    static int s_attr_done = 0;
    if (!s_attr_done) {
        cudaFuncSetAttribute(k_gemm<HIDDEN,0>, cudaFuncAttributeMaxDynamicSharedMemorySize, GEMM_DSMEM);
        cudaFuncSetAttribute(k_gemm<INTER, 1>, cudaFuncAttributeMaxDynamicSharedMemorySize, GEMM_DSMEM);
        cudaFuncSetAttribute(k_prep2<HIDDEN,true >, cudaFuncAttributeMaxDynamicSharedMemorySize, PREP_SMEM);
        cudaFuncSetAttribute(k_prep2<INTER, false>, cudaFuncAttributeMaxDynamicSharedMemorySize, PREP_SMEM);
        s_attr_done = 1;
    }

    k_trig<<<(NROT*HIDDEN/2 + 255)/256, 256>>>(gup_a, dwn_a);                          // 1
    k_prep2<HIDDEN, true ><<<(NE*O2/128)*16,    256, PREP_SMEM>>>(gup_w, gup_p, gup_ch);// 2
    k_hrot<<<(TOKENS*16 + 7)/8, 256>>>(hidden, gup_p, gup_ch, topk, out);              // 3
    k_gemm<HIDDEN, 0><<<dim3(NE*TPE, INTER/64), 256, GEMM_DSMEM>>>(topw, out);         // 4 (profiled)
    k_prep2<INTER,  false><<<(NE*HIDDEN/128)*6, 256, PREP_SMEM>>>(dwn_w, dwn_p, dwn_ch);// 5
    k_irot<<<(NASSIGN*6 + 7)/8, 256>>>(dwn_p, dwn_ch);                                 // 6
    k_gemm<INTER,  1><<<dim3(NE*TPE, HIDDEN/128), 256, GEMM_DSMEM>>>(topw, out);       // 7
}

// round 14
// speedup vs baseline: 1.2173x; 1.1653x over previous
#include <cuda_runtime.h>
#include <cuda_fp16.h>
#include <math.h>
#include <stdint.h>

#define NE      8
#define HIDDEN  2048
#define INTER   768
#define O2      (2*INTER)     // 1536
#define NROT    4
#define TOKENS  4096
#define NASSIGN (TOKENS*2)    // 8192
#define CAP     NASSIGN
#define QMAXF   15.0f
#define TPE     12            // max m-tiles per expert (cap 1536 rows)

// ---------------- scratch (device globals; no allocation allowed) ----------------
__device__ __half g_gup[NE*O2*HIDDEN];       // quantized gate_up weights, ROTATED basis
__device__ __half g_dwn[NE*HIDDEN*INTER];    // quantized down weights, ROTATED basis
__device__ __half g_h[TOKENS*HIDDEN];        // rotated hidden states (fp16)
__device__ __half g_i[NASSIGN*INTER];        // inter activations (fp16)
__device__ int    g_cnt[NE];
__device__ int    g_perm[NE*CAP];
__device__ float  g_cgu[NROT*HIDDEN/2], g_sgu[NROT*HIDDEN/2];
__device__ float  g_cdn[NROT*INTER/2],  g_sdn[NROT*INTER/2];

__device__ __forceinline__ uint32_t smem_u32(const void* p) {
    uint32_t a;
    asm("{ .reg .u64 t; cvta.to.shared.u64 t, %1; cvt.u32.u64 %0, t; }" : "=r"(a) : "l"(p));
    return a;
}

// ---------------- trig tables (double; fast-math immune) + zero counters ----------
__global__ void k_trig(const float* __restrict__ ga, const float* __restrict__ da) {
    int i = blockIdx.x*blockDim.x + threadIdx.x;
    if (i < NE) g_cnt[i] = 0;
    if (i < NROT*HIDDEN/2) {
        double a = (double)ga[i];
        g_cgu[i] = (float)cos(a);
        g_sgu[i] = (float)sin(a);
    }
    if (i < NROT*INTER/2) {
        double a = (double)da[i];
        g_cdn[i] = (float)cos(a);
        g_sdn[i] = (float)sin(a);
    }
}

// ---------------- warp-level group rotation (forward) ----------------
template<int IN>
__device__ __forceinline__ void warp_rot_fwd(float* w, int lane,
                                             const int* __restrict__ prs,
                                             const float* __restrict__ ctab,
                                             const float* __restrict__ stab) {
    #pragma unroll
    for (int r = 0; r < NROT; r++) {
        const int*   pr = prs + r*IN;
        const float* cr = ctab + r*(IN/2);
        const float* sr = stab + r*(IN/2);
        int4 pp = *(const int4*)(pr + lane*4);
        float c0 = cr[2*lane],   s0 = sr[2*lane];
        float c1 = cr[2*lane+1], s1 = sr[2*lane+1];
        float wi = w[pp.x], wj = w[pp.y];
        w[pp.x] = __fsub_rn(__fmul_rn(c0, wi), __fmul_rn(s0, wj));
        w[pp.y] = __fadd_rn(__fmul_rn(s0, wi), __fmul_rn(c0, wj));
        float wi2 = w[pp.z], wj2 = w[pp.w];
        w[pp.z] = __fsub_rn(__fmul_rn(c1, wi2), __fmul_rn(s1, wj2));
        w[pp.w] = __fadd_rn(__fmul_rn(s1, wi2), __fmul_rn(c1, wj2));
        __syncwarp();
    }
}

// ---------------- weight prep: scale -> rotate -> fake-quant -> fp16 (rotated) ----
template<int IN, bool GU>
__global__ __launch_bounds__(256) void k_prep(const float* __restrict__ W,
                                              const int*   __restrict__ pairs,
                                              const float* __restrict__ ch) {
    constexpr int NG = IN/128;
    constexpr int ROWS = GU ? NE*O2 : NE*HIDDEN;
    __shared__ float sw[8][128];
    const int wid = threadIdx.x >> 5, lane = threadIdx.x & 31;
    const int gid = blockIdx.x*8 + wid;
    if (gid >= ROWS*NG) return;
    const int row = gid / NG, g = gid % NG;

    const float* src = W + (size_t)row*IN + g*128;
    const float* chp = ch + g*128;
    const float* ctab = (GU ? g_cgu : g_cdn) + g*64;
    const float* stab = (GU ? g_sgu : g_sdn) + g*64;
    const int*   prs  = pairs + g*128;
    float* w = sw[wid];

    float4 v  = *(const float4*)(src + lane*4);
    float4 cv = *(const float4*)(chp + lane*4);
    w[lane*4+0] = __fmul_rn(v.x, cv.x);
    w[lane*4+1] = __fmul_rn(v.y, cv.y);
    w[lane*4+2] = __fmul_rn(v.z, cv.z);
    w[lane*4+3] = __fmul_rn(v.w, cv.w);
    __syncwarp();

    warp_rot_fwd<IN>(w, lane, prs, ctab, stab);

    float a0 = w[lane*4+0], a1 = w[lane*4+1], a2 = w[lane*4+2], a3 = w[lane*4+3];
    float mx = fmaxf(fmaxf(a0, a1), fmaxf(a2, a3));
    float mn = fminf(fminf(a0, a1), fminf(a2, a3));
    #pragma unroll
    for (int o = 16; o; o >>= 1) {
        mx = fmaxf(mx, __shfl_xor_sync(0xffffffffu, mx, o));
        mn = fminf(mn, __shfl_xor_sync(0xffffffffu, mn, o));
    }
    float d  = fmaxf(__fsub_rn(mx, mn), 1e-5f);
    float sc = __fdiv_rn(d, QMAXF);
    float z  = rintf(__fdiv_rn(__fmul_rn(mn, -1.0f), sc));

    __half h[4];
    float av[4] = {a0, a1, a2, a3};
    #pragma unroll
    for (int k = 0; k < 4; k++) {
        float q = __fadd_rn(rintf(__fdiv_rn(av[k], sc)), z);
        q = fminf(fmaxf(q, 0.0f), QMAXF);
        h[k] = __float2half_rn(__fmul_rn(__fsub_rn(q, z), sc));
    }
    __half* out = (GU ? g_gup : g_dwn) + (size_t)row*IN + g*128 + lane*4;
    *(__half2*)(out)     = __halves2half2(h[0], h[1]);
    *(__half2*)(out + 2) = __halves2half2(h[2], h[3]);
}

// ---------------- hidden: x' = R_gu(x / ch_gu) -> fp16; zero out; + routing -------
__global__ __launch_bounds__(256) void k_hrot(const float* __restrict__ hs,
                                              const int*   __restrict__ pairs,
                                              const float* __restrict__ ch,
                                              const int*   __restrict__ topk,
                                              float* __restrict__ out) {
    constexpr int IN = HIDDEN, NG = IN/128;
    __shared__ float sw[8][128];
    const int tid = threadIdx.x;
    const int wid = tid >> 5, lane = tid & 31;

    int rid = blockIdx.x*256 + tid;
    if (rid < NASSIGN) {
        int e = topk[rid];
        int slot = atomicAdd(&g_cnt[e], 1);
        g_perm[e*CAP + slot] = rid;
    }

    const int gid = blockIdx.x*8 + wid;
    if (gid >= TOKENS*NG) return;
    const int row = gid / NG, g = gid % NG;

    const float* src = hs + (size_t)row*IN + g*128;
    const float* chp = ch + g*128;
    float* w = sw[wid];

    float4 v  = *(const float4*)(src + lane*4);
    float4 cv = *(const float4*)(chp + lane*4);
    w[lane*4+0] = __fdiv_rn(v.x, cv.x);
    w[lane*4+1] = __fdiv_rn(v.y, cv.y);
    w[lane*4+2] = __fdiv_rn(v.z, cv.z);
    w[lane*4+3] = __fdiv_rn(v.w, cv.w);
    __syncwarp();

    warp_rot_fwd<IN>(w, lane, pairs + g*128, g_cgu + g*64, g_sgu + g*64);

    __half* o = g_h + (size_t)row*IN + g*128 + lane*4;
    *(__half2*)(o)     = __floats2half2_rn(w[lane*4+0], w[lane*4+1]);
    *(__half2*)(o + 2) = __floats2half2_rn(w[lane*4+2], w[lane*4+3]);
    *(float4*)(out + (size_t)row*IN + g*128 + lane*4) = make_float4(0.f, 0.f, 0.f, 0.f);
}

// ---------------- inter: i' = R_dn(inter / ch_dn), in place on g_i ----------------
__global__ __launch_bounds__(256) void k_irot(const int*   __restrict__ pairs,
                                              const float* __restrict__ ch) {
    constexpr int IN = INTER, NG = IN/128;
    __shared__ float sw[8][128];
    const int wid = threadIdx.x >> 5, lane = threadIdx.x & 31;
    const int gid = blockIdx.x*8 + wid;
    if (gid >= NASSIGN*NG) return;
    const int row = gid / NG, g = gid % NG;

    __half* base = g_i + (size_t)row*IN + g*128 + lane*4;
    const float* chp = ch + g*128 + lane*4;
    float* w = sw[wid];

    __half2 v01 = *(__half2*)(base);
    __half2 v23 = *(__half2*)(base + 2);
    w[lane*4+0] = __fdiv_rn(__half2float(__low2half(v01)),  chp[0]);
    w[lane*4+1] = __fdiv_rn(__half2float(__high2half(v01)), chp[1]);
    w[lane*4+2] = __fdiv_rn(__half2float(__low2half(v23)),  chp[2]);
    w[lane*4+3] = __fdiv_rn(__half2float(__high2half(v23)), chp[3]);
    __syncwarp();

    warp_rot_fwd<IN>(w, lane, pairs + g*128, g_cdn + g*64, g_sdn + g*64);

    *(__half2*)(base)     = __floats2half2_rn(w[lane*4+0], w[lane*4+1]);
    *(__half2*)(base + 2) = __floats2half2_rn(w[lane*4+2], w[lane*4+3]);
}

// ---------------- grouped HMMA GEMM (R7 config) + B-side ldmatrix.x4 --------------
#define PAD 40                      // halves per smem row (80B)
#define BUF_H (128*PAD)             // halves per buffer
#define GEMM_DSMEM (6*BUF_H*2)      // 3 stages x (A+B) = 61440 B

template<int KD, int MODE>
__global__ __launch_bounds__(256, 2) void k_gemm(const float* __restrict__ topw,
                                                 float* __restrict__ out) {
    const int e  = blockIdx.x / TPE;
    const int m0 = (blockIdx.x % TPE) * 128;
    if (m0 >= g_cnt[e]) return;
    const int y  = blockIdx.y;
    const int n0 = y * 128;
    constexpr int NST = KD / 32;

    extern __shared__ __align__(16) __half dsm[];
    __shared__ int s_arow[128];

    const int tid  = threadIdx.x;
    const int wid  = tid >> 5, lane = tid & 31;

    if (tid < 128) {
        int m = m0 + tid;
        s_arow[tid] = (m < g_cnt[e]) ? g_perm[e*CAP + m] : -1;
    }
    __syncthreads();

    const __half* Ag = MODE ? g_i : g_h;
    const __half* Bg = (MODE ? g_dwn : g_gup) + (size_t)e*(MODE?HIDDEN:O2)*KD;

    const __half* srcA[2]; uint32_t dstA[2]; uint32_t szA[2];
    const __half* srcB[2];
    #pragma unroll
    for (int j = 0; j < 2; j++) {
        int idx = tid*2 + j;            // 0..511
        int r = idx >> 2, c16 = idx & 3;
        int a = s_arow[r];
        int arowg = MODE ? a : (a >> 1);
        srcA[j] = (a >= 0) ? Ag + (size_t)arowg*KD + c16*8 : Ag;
        szA[j]  = (a >= 0) ? 16u : 0u;
        dstA[j] = (uint32_t)((r*PAD + c16*8) * 2);
        int brow;
        if (MODE) brow = n0 + r;
        else      brow = (r < 64) ? (y*64 + r) : (INTER + y*64 + (r - 64));
        srcB[j] = Bg + (size_t)brow*KD + c16*8;
    }
    uint32_t aB[3], bB[3];
    #pragma unroll
    for (int st = 0; st < 3; st++) {
        aB[st] = smem_u32(dsm + st*BUF_H);
        bB[st] = smem_u32(dsm + 3*BUF_H + st*BUF_H);
    }

    float acc[4][4][4];
    #pragma unroll
    for (int i = 0; i < 4; i++)
        #pragma unroll
        for (int j = 0; j < 4; j++)
            #pragma unroll
            for (int q = 0; q < 4; q++) acc[i][j][q] = 0.0f;

    const int mBase = (wid & 1) * 64;
    const int nBase = (wid >> 1) * 32;
    uint32_t aoff[4], boff4[2];
    #pragma unroll
    for (int mi = 0; mi < 4; mi++) {
        int r = mBase + mi*16 + (lane & 15);
        int kk = (lane >> 4) * 8;
        aoff[mi] = (uint32_t)((r*PAD + kk) * 2);
    }
    // B ldmatrix.x4: nj covers 16 rows (2 ni blocks) x 16 k.
    // lanes 0-7: rows +0..7 @k0 | 8-15: rows +0..7 @k8 | 16-23: rows +8..15 @k0 | 24-31: @k8
    #pragma unroll
    for (int nj = 0; nj < 2; nj++) {
        int r = nBase + nj*16 + (lane & 7) + ((lane >> 4) << 3);
        int kk = ((lane >> 3) & 1) * 8;
        boff4[nj] = (uint32_t)((r*PAD + kk) * 2);
    }

    #define PREFETCH(st) do {                                                  \
        const int k0_ = (st) * 32;                                             \
        uint32_t ab = aB[(st) % 3], bb = bB[(st) % 3];                         \
        _Pragma("unroll")                                                      \
        for (int j = 0; j < 2; j++) {                                          \
            asm volatile("cp.async.ca.shared.global [%0], [%1], 16, %2;"       \
                :: "r"(ab + dstA[j]), "l"(srcA[j] + k0_), "r"(szA[j]));        \
            asm volatile("cp.async.ca.shared.global [%0], [%1], 16;"           \
                :: "r"(bb + dstA[j]), "l"(srcB[j] + k0_));                     \
        }                                                                      \
        asm volatile("cp.async.commit_group;");                                \
    } while (0)

    PREFETCH(0);
    PREFETCH(1);

    for (int s = 0; s < NST; s++) {
        asm volatile("cp.async.wait_group 1;");
        __syncthreads();
        if (s + 2 < NST) PREFETCH(s + 2);
        else asm volatile("cp.async.commit_group;");
        uint32_t ab = aB[s % 3], bb = bB[s % 3];
        #pragma unroll
        for (int ks = 0; ks < 2; ks++) {
            uint32_t a[4][4], b[4][2];
            #pragma unroll
            for (int mi = 0; mi < 4; mi++)
                asm volatile("ldmatrix.sync.aligned.m8n8.x4.shared.b16 {%0,%1,%2,%3}, [%4];"
                    : "=r"(a[mi][0]), "=r"(a[mi][1]), "=r"(a[mi][2]), "=r"(a[mi][3])
                    : "r"(ab + aoff[mi] + ks*32));
            #pragma unroll
            for (int nj = 0; nj < 2; nj++)
                asm volatile("ldmatrix.sync.aligned.m8n8.x4.shared.b16 {%0,%1,%2,%3}, [%4];"
                    : "=r"(b[2*nj][0]), "=r"(b[2*nj][1]),
                      "=r"(b[2*nj+1][0]), "=r"(b[2*nj+1][1])
                    : "r"(bb + boff4[nj] + ks*32));
            #pragma unroll
            for (int mi = 0; mi < 4; mi++)
                #pragma unroll
                for (int ni = 0; ni < 4; ni++)
                    asm volatile(
                        "mma.sync.aligned.m16n8k16.row.col.f32.f16.f16.f32 "
                        "{%0,%1,%2,%3}, {%4,%5,%6,%7}, {%8,%9}, {%0,%1,%2,%3};"
                        : "+f"(acc[mi][ni][0]), "+f"(acc[mi][ni][1]),
                          "+f"(acc[mi][ni][2]), "+f"(acc[mi][ni][3])
                        : "r"(a[mi][0]), "r"(a[mi][1]), "r"(a[mi][2]), "r"(a[mi][3]),
                          "r"(b[ni][0]), "r"(b[ni][1]));
        }
    }

    const int qrow = lane >> 2, qcol = (lane & 3) * 2;

    if (MODE == 0) {
        __syncthreads();   // all warps done reading dsm before reuse as sg
        float* sg = (float*)dsm;   // 128 x 64 fp32 = 32 KB
        if (wid < 4) {
            #pragma unroll
            for (int mi = 0; mi < 4; mi++) {
                int r0 = mBase + mi*16 + qrow;
                #pragma unroll
                for (int ni = 0; ni < 4; ni++) {
                    int c = nBase + ni*8 + qcol;
                    sg[r0*64 + c]     = acc[mi][ni][0];
                    sg[r0*64 + c + 1] = acc[mi][ni][1];
                    sg[(r0+8)*64 + c]     = acc[mi][ni][2];
                    sg[(r0+8)*64 + c + 1] = acc[mi][ni][3];
                }
            }
        }
        __syncthreads();
        if (wid >= 4) {
            #pragma unroll
            for (int mi = 0; mi < 4; mi++) {
                int r0 = mBase + mi*16 + qrow;
                int a0 = s_arow[r0], a1 = s_arow[r0 + 8];
                #pragma unroll
                for (int ni = 0; ni < 4; ni++) {
                    int c = (nBase - 64) + ni*8 + qcol;
                    if (a0 >= 0) {
                        float gA = sg[r0*64 + c], gB = sg[r0*64 + c + 1];
                        float vA = (gA / (1.0f + expf(-gA))) * acc[mi][ni][0];
                        float vB = (gB / (1.0f + expf(-gB))) * acc[mi][ni][1];
                        *(__half2*)&g_i[(size_t)a0*INTER + y*64 + c] = __floats2half2_rn(vA, vB);
                    }
                    if (a1 >= 0) {
                        float gA = sg[(r0+8)*64 + c], gB = sg[(r0+8)*64 + c + 1];
                        float vA = (gA / (1.0f + expf(-gA))) * acc[mi][ni][2];
                        float vB = (gB / (1.0f + expf(-gB))) * acc[mi][ni][3];
                        *(__half2*)&g_i[(size_t)a1*INTER + y*64 + c] = __floats2half2_rn(vA, vB);
                    }
                }
            }
        }
    } else {
        #pragma unroll
        for (int mi = 0; mi < 4; mi++) {
            int r0 = mBase + mi*16 + qrow;
            int a0 = s_arow[r0], a1 = s_arow[r0 + 8];
            float w0 = 0.f, w1 = 0.f;
            float *O0 = nullptr, *O1 = nullptr;
            if (a0 >= 0) { w0 = topw[a0]; O0 = out + (size_t)(a0 >> 1)*HIDDEN + n0; }
            if (a1 >= 0) { w1 = topw[a1]; O1 = out + (size_t)(a1 >> 1)*HIDDEN + n0; }
            #pragma unroll
            for (int ni = 0; ni < 4; ni++) {
                int c = nBase + ni*8 + qcol;
                if (O0) {
                    atomicAdd(&O0[c],     w0 * acc[mi][ni][0]);
                    atomicAdd(&O0[c + 1], w0 * acc[mi][ni][1]);
                }
                if (O1) {
                    atomicAdd(&O1[c],     w1 * acc[mi][ni][2]);
                    atomicAdd(&O1[c + 1], w1 * acc[mi][ni][3]);
                }
            }
        }
    }
}

// ---------------- launch ----------------
extern "C" void kernel_launch(void* const* d_in, const int* in_sizes, int n_in,
                              void* d_out, int out_size) {
    const float* hidden  = (const float*)d_in[0];
    const int*   topk    = (const int*)  d_in[1];
    const float* topw    = (const float*)d_in[2];
    const float* gup_w   = (const float*)d_in[3];
    const float* dwn_w   = (const float*)d_in[4];
    const int*   gup_p   = (const int*)  d_in[5];
    const float* gup_a   = (const float*)d_in[6];
    const int*   dwn_p   = (const int*)  d_in[7];
    const float* dwn_a   = (const float*)d_in[8];
    const float* gup_ch  = (const float*)d_in[9];
    const float* dwn_ch  = (const float*)d_in[10];
    float* out = (float*)d_out;

    static int s_attr_done = 0;
    if (!s_attr_done) {
        cudaFuncSetAttribute(k_gemm<HIDDEN,0>, cudaFuncAttributeMaxDynamicSharedMemorySize, GEMM_DSMEM);
        cudaFuncSetAttribute(k_gemm<INTER, 1>, cudaFuncAttributeMaxDynamicSharedMemorySize, GEMM_DSMEM);
        s_attr_done = 1;
    }

    k_trig<<<(NROT*HIDDEN/2 + 255)/256, 256>>>(gup_a, dwn_a);                   // 1
    k_prep<HIDDEN, true ><<<(NE*O2*16 + 7)/8,    256>>>(gup_w, gup_p, gup_ch);  // 2
    k_hrot<<<(TOKENS*16 + 7)/8, 256>>>(hidden, gup_p, gup_ch, topk, out);       // 3
    k_gemm<HIDDEN, 0><<<dim3(NE*TPE, INTER/64), 256, GEMM_DSMEM>>>(topw, out);  // 4 (profiled)
    k_prep<INTER,  false><<<(NE*HIDDEN*6 + 7)/8, 256>>>(dwn_w, dwn_p, dwn_ch);  // 5
    k_irot<<<(NASSIGN*6 + 7)/8, 256>>>(dwn_p, dwn_ch);                          // 6
    k_gemm<INTER,  1><<<dim3(NE*TPE, HIDDEN/128), 256, GEMM_DSMEM>>>(topw, out);// 7
}

// round 17
// speedup vs baseline: 1.2904x; 1.0601x over previous
#include <cuda_runtime.h>
#include <cuda_fp16.h>
#include <math.h>
#include <stdint.h>

#define NE      8
#define HIDDEN  2048
#define INTER   768
#define O2      (2*INTER)     // 1536
#define NROT    4
#define TOKENS  4096
#define NASSIGN (TOKENS*2)    // 8192
#define CAP     NASSIGN
#define QMAXF   15.0f
#define TPE     12            // max m-tiles per expert (cap 1536 rows)

// ---------------- scratch (device globals; no allocation allowed) ----------------
__device__ __half g_gup[NE*O2*HIDDEN];       // quantized gate_up weights, ROTATED basis
__device__ __half g_dwn[NE*HIDDEN*INTER];    // quantized down weights, ROTATED basis
__device__ __half g_h[TOKENS*HIDDEN];        // rotated hidden states (fp16)
__device__ __half g_i[NASSIGN*INTER];        // inter activations (fp16)
__device__ int    g_cnt[NE];
__device__ int    g_perm[NE*CAP];
__device__ float  g_cgu[NROT*HIDDEN/2], g_sgu[NROT*HIDDEN/2];
__device__ float  g_cdn[NROT*INTER/2],  g_sdn[NROT*INTER/2];

__device__ __forceinline__ uint32_t smem_u32(const void* p) {
    uint32_t a;
    asm("{ .reg .u64 t; cvta.to.shared.u64 t, %1; cvt.u32.u64 %0, t; }" : "=r"(a) : "l"(p));
    return a;
}

// ---------------- trig tables (double; fast-math immune) + zero counters ----------
__global__ void k_trig(const float* __restrict__ ga, const float* __restrict__ da) {
    int i = blockIdx.x*blockDim.x + threadIdx.x;
    if (i < NE) g_cnt[i] = 0;
    if (i < NROT*HIDDEN/2) {
        double a = (double)ga[i];
        g_cgu[i] = (float)cos(a);
        g_sgu[i] = (float)sin(a);
    }
    if (i < NROT*INTER/2) {
        double a = (double)da[i];
        g_cdn[i] = (float)cos(a);
        g_sdn[i] = (float)sin(a);
    }
}

// ---------------- warp-level group rotation (forward), TWO rows per warp ----------
// w0, w1: two 128-float rows of the same group (second staggered +132 in smem).
// Tables (pairs/cos/sin) loaded once, applied to both rows. Per-row op sequence
// is identical to the reference chain (bit-exact).
template<int IN>
__device__ __forceinline__ void warp_rot_fwd2(float* w0, float* w1, int lane,
                                              const int* __restrict__ prs,
                                              const float* __restrict__ ctab,
                                              const float* __restrict__ stab) {
    #pragma unroll
    for (int r = 0; r < NROT; r++) {
        const int*   pr = prs + r*IN;
        const float* cr = ctab + r*(IN/2);
        const float* sr = stab + r*(IN/2);
        int4 pp = *(const int4*)(pr + lane*4);
        float c0 = cr[2*lane],   s0 = sr[2*lane];
        float c1 = cr[2*lane+1], s1 = sr[2*lane+1];
        {
            float wi = w0[pp.x], wj = w0[pp.y];
            w0[pp.x] = __fsub_rn(__fmul_rn(c0, wi), __fmul_rn(s0, wj));
            w0[pp.y] = __fadd_rn(__fmul_rn(s0, wi), __fmul_rn(c0, wj));
            float wi2 = w0[pp.z], wj2 = w0[pp.w];
            w0[pp.z] = __fsub_rn(__fmul_rn(c1, wi2), __fmul_rn(s1, wj2));
            w0[pp.w] = __fadd_rn(__fmul_rn(s1, wi2), __fmul_rn(c1, wj2));
        }
        {
            float wi = w1[pp.x], wj = w1[pp.y];
            w1[pp.x] = __fsub_rn(__fmul_rn(c0, wi), __fmul_rn(s0, wj));
            w1[pp.y] = __fadd_rn(__fmul_rn(s0, wi), __fmul_rn(c0, wj));
            float wi2 = w1[pp.z], wj2 = w1[pp.w];
            w1[pp.z] = __fsub_rn(__fmul_rn(c1, wi2), __fmul_rn(s1, wj2));
            w1[pp.w] = __fadd_rn(__fmul_rn(s1, wi2), __fmul_rn(c1, wj2));
        }
        __syncwarp();
    }
}

// ---------------- quant helper: warp-reduce min/max of one row, emit fp16 --------
__device__ __forceinline__ void quant_row_out(const float* a /*4 vals*/,
                                              __half* out, int lane) {
    float mx = fmaxf(fmaxf(a[0], a[1]), fmaxf(a[2], a[3]));
    float mn = fminf(fminf(a[0], a[1]), fminf(a[2], a[3]));
    #pragma unroll
    for (int o = 16; o; o >>= 1) {
        mx = fmaxf(mx, __shfl_xor_sync(0xffffffffu, mx, o));
        mn = fminf(mn, __shfl_xor_sync(0xffffffffu, mn, o));
    }
    float d  = fmaxf(__fsub_rn(mx, mn), 1e-5f);
    float sc = __fdiv_rn(d, QMAXF);
    float z  = rintf(__fdiv_rn(__fmul_rn(mn, -1.0f), sc));
    __half h[4];
    #pragma unroll
    for (int k = 0; k < 4; k++) {
        float q = __fadd_rn(rintf(__fdiv_rn(a[k], sc)), z);
        q = fminf(fmaxf(q, 0.0f), QMAXF);
        h[k] = __float2half_rn(__fmul_rn(__fsub_rn(q, z), sc));
    }
    *(__half2*)(out + lane*4)     = __halves2half2(h[0], h[1]);
    *(__half2*)(out + lane*4 + 2) = __halves2half2(h[2], h[3]);
}

// ---------------- weight prep: 2 rows per warp ----------------
template<int IN, bool GU>
__global__ __launch_bounds__(256) void k_prep(const float* __restrict__ W,
                                              const int*   __restrict__ pairs,
                                              const float* __restrict__ ch) {
    constexpr int NG = IN/128;
    constexpr int ROWS = GU ? NE*O2 : NE*HIDDEN;
    __shared__ float sw[8][264];     // [row0: 0..127][row1: 132..259]
    const int wid = threadIdx.x >> 5, lane = threadIdx.x & 31;
    const int gid = blockIdx.x*8 + wid;
    if (gid >= (ROWS/2)*NG) return;
    const int rp = gid / NG, g = gid % NG;
    const int row0 = 2*rp, row1 = 2*rp + 1;

    const float* chp = ch + g*128;
    const float* ctab = (GU ? g_cgu : g_cdn) + g*64;
    const float* stab = (GU ? g_sgu : g_sdn) + g*64;
    float* w0 = sw[wid];
    float* w1 = sw[wid] + 132;

    float4 cv = *(const float4*)(chp + lane*4);
    {
        float4 v = *(const float4*)(W + (size_t)row0*IN + g*128 + lane*4);
        w0[lane*4+0] = __fmul_rn(v.x, cv.x);
        w0[lane*4+1] = __fmul_rn(v.y, cv.y);
        w0[lane*4+2] = __fmul_rn(v.z, cv.z);
        w0[lane*4+3] = __fmul_rn(v.w, cv.w);
    }
    {
        float4 v = *(const float4*)(W + (size_t)row1*IN + g*128 + lane*4);
        w1[lane*4+0] = __fmul_rn(v.x, cv.x);
        w1[lane*4+1] = __fmul_rn(v.y, cv.y);
        w1[lane*4+2] = __fmul_rn(v.z, cv.z);
        w1[lane*4+3] = __fmul_rn(v.w, cv.w);
    }
    __syncwarp();

    warp_rot_fwd2<IN>(w0, w1, lane, pairs + g*128, ctab, stab);

    __half* outb = (GU ? g_gup : g_dwn);
    quant_row_out(w0 + lane*4, outb + (size_t)row0*IN + g*128, lane);
    quant_row_out(w1 + lane*4, outb + (size_t)row1*IN + g*128, lane);
}

// ---------------- hidden: 2 tokens per warp; zero out; + routing -------
__global__ __launch_bounds__(256) void k_hrot(const float* __restrict__ hs,
                                              const int*   __restrict__ pairs,
                                              const float* __restrict__ ch,
                                              const int*   __restrict__ topk,
                                              float* __restrict__ out) {
    constexpr int IN = HIDDEN, NG = IN/128;
    __shared__ float sw[8][264];
    const int tid = threadIdx.x;
    const int wid = tid >> 5, lane = tid & 31;

    int rid = blockIdx.x*256 + tid;
    if (rid < NASSIGN) {
        int e = topk[rid];
        int slot = atomicAdd(&g_cnt[e], 1);
        g_perm[e*CAP + slot] = rid;
    }

    const int gid = blockIdx.x*8 + wid;
    if (gid >= (TOKENS/2)*NG) return;
    const int rp = gid / NG, g = gid % NG;
    const int row0 = 2*rp, row1 = 2*rp + 1;

    const float* chp = ch + g*128;
    float* w0 = sw[wid];
    float* w1 = sw[wid] + 132;

    float4 cv = *(const float4*)(chp + lane*4);
    {
        float4 v = *(const float4*)(hs + (size_t)row0*IN + g*128 + lane*4);
        w0[lane*4+0] = __fdiv_rn(v.x, cv.x);
        w0[lane*4+1] = __fdiv_rn(v.y, cv.y);
        w0[lane*4+2] = __fdiv_rn(v.z, cv.z);
        w0[lane*4+3] = __fdiv_rn(v.w, cv.w);
    }
    {
        float4 v = *(const float4*)(hs + (size_t)row1*IN + g*128 + lane*4);
        w1[lane*4+0] = __fdiv_rn(v.x, cv.x);
        w1[lane*4+1] = __fdiv_rn(v.y, cv.y);
        w1[lane*4+2] = __fdiv_rn(v.z, cv.z);
        w1[lane*4+3] = __fdiv_rn(v.w, cv.w);
    }
    __syncwarp();

    warp_rot_fwd2<IN>(w0, w1, lane, pairs + g*128, g_cgu + g*64, g_sgu + g*64);

    {
        __half* o = g_h + (size_t)row0*IN + g*128 + lane*4;
        *(__half2*)(o)     = __floats2half2_rn(w0[lane*4+0], w0[lane*4+1]);
        *(__half2*)(o + 2) = __floats2half2_rn(w0[lane*4+2], w0[lane*4+3]);
        *(float4*)(out + (size_t)row0*IN + g*128 + lane*4) = make_float4(0.f,0.f,0.f,0.f);
    }
    {
        __half* o = g_h + (size_t)row1*IN + g*128 + lane*4;
        *(__half2*)(o)     = __floats2half2_rn(w1[lane*4+0], w1[lane*4+1]);
        *(__half2*)(o + 2) = __floats2half2_rn(w1[lane*4+2], w1[lane*4+3]);
        *(float4*)(out + (size_t)row1*IN + g*128 + lane*4) = make_float4(0.f,0.f,0.f,0.f);
    }
}

// ---------------- inter: 2 assignments per warp, in place on g_i ----------------
__global__ __launch_bounds__(256) void k_irot(const int*   __restrict__ pairs,
                                              const float* __restrict__ ch) {
    constexpr int IN = INTER, NG = IN/128;
    __shared__ float sw[8][264];
    const int wid = threadIdx.x >> 5, lane = threadIdx.x & 31;
    const int gid = blockIdx.x*8 + wid;
    if (gid >= (NASSIGN/2)*NG) return;
    const int rp = gid / NG, g = gid % NG;
    const int row0 = 2*rp, row1 = 2*rp + 1;

    const float* chp = ch + g*128 + lane*4;
    float* w0 = sw[wid];
    float* w1 = sw[wid] + 132;
    __half* b0 = g_i + (size_t)row0*IN + g*128 + lane*4;
    __half* b1 = g_i + (size_t)row1*IN + g*128 + lane*4;

    {
        __half2 v01 = *(__half2*)(b0);
        __half2 v23 = *(__half2*)(b0 + 2);
        w0[lane*4+0] = __fdiv_rn(__half2float(__low2half(v01)),  chp[0]);
        w0[lane*4+1] = __fdiv_rn(__half2float(__high2half(v01)), chp[1]);
        w0[lane*4+2] = __fdiv_rn(__half2float(__low2half(v23)),  chp[2]);
        w0[lane*4+3] = __fdiv_rn(__half2float(__high2half(v23)), chp[3]);
    }
    {
        __half2 v01 = *(__half2*)(b1);
        __half2 v23 = *(__half2*)(b1 + 2);
        w1[lane*4+0] = __fdiv_rn(__half2float(__low2half(v01)),  chp[0]);
        w1[lane*4+1] = __fdiv_rn(__half2float(__high2half(v01)), chp[1]);
        w1[lane*4+2] = __fdiv_rn(__half2float(__low2half(v23)),  chp[2]);
        w1[lane*4+3] = __fdiv_rn(__half2float(__high2half(v23)), chp[3]);
    }
    __syncwarp();

    warp_rot_fwd2<IN>(w0, w1, lane, pairs + g*128, g_cdn + g*64, g_sdn + g*64);

    *(__half2*)(b0)     = __floats2half2_rn(w0[lane*4+0], w0[lane*4+1]);
    *(__half2*)(b0 + 2) = __floats2half2_rn(w0[lane*4+2], w0[lane*4+3]);
    *(__half2*)(b1)     = __floats2half2_rn(w1[lane*4+0], w1[lane*4+1]);
    *(__half2*)(b1 + 2) = __floats2half2_rn(w1[lane*4+2], w1[lane*4+3]);
}

// ---------------- grouped HMMA GEMM (R14 config, unchanged) -----------------------
#define PAD 40                      // halves per smem row (80B)
#define BUF_H (128*PAD)             // halves per buffer
#define GEMM_DSMEM (6*BUF_H*2)      // 3 stages x (A+B) = 61440 B

template<int KD, int MODE>
__global__ __launch_bounds__(256, 2) void k_gemm(const float* __restrict__ topw,
                                                 float* __restrict__ out) {
    const int e  = blockIdx.x / TPE;
    const int m0 = (blockIdx.x % TPE) * 128;
    if (m0 >= g_cnt[e]) return;
    const int y  = blockIdx.y;
    const int n0 = y * 128;
    constexpr int NST = KD / 32;

    extern __shared__ __align__(16) __half dsm[];
    __shared__ int s_arow[128];

    const int tid  = threadIdx.x;
    const int wid  = tid >> 5, lane = tid & 31;

    if (tid < 128) {
        int m = m0 + tid;
        s_arow[tid] = (m < g_cnt[e]) ? g_perm[e*CAP + m] : -1;
    }
    __syncthreads();

    const __half* Ag = MODE ? g_i : g_h;
    const __half* Bg = (MODE ? g_dwn : g_gup) + (size_t)e*(MODE?HIDDEN:O2)*KD;

    const __half* srcA[2]; uint32_t dstA[2]; uint32_t szA[2];
    const __half* srcB[2];
    #pragma unroll
    for (int j = 0; j < 2; j++) {
        int idx = tid*2 + j;            // 0..511
        int r = idx >> 2, c16 = idx & 3;
        int a = s_arow[r];
        int arowg = MODE ? a : (a >> 1);
        srcA[j] = (a >= 0) ? Ag + (size_t)arowg*KD + c16*8 : Ag;
        szA[j]  = (a >= 0) ? 16u : 0u;
        dstA[j] = (uint32_t)((r*PAD + c16*8) * 2);
        int brow;
        if (MODE) brow = n0 + r;
        else      brow = (r < 64) ? (y*64 + r) : (INTER + y*64 + (r - 64));
        srcB[j] = Bg + (size_t)brow*KD + c16*8;
    }
    uint32_t aB[3], bB[3];
    #pragma unroll
    for (int st = 0; st < 3; st++) {
        aB[st] = smem_u32(dsm + st*BUF_H);
        bB[st] = smem_u32(dsm + 3*BUF_H + st*BUF_H);
    }

    float acc[4][4][4];
    #pragma unroll
    for (int i = 0; i < 4; i++)
        #pragma unroll
        for (int j = 0; j < 4; j++)
            #pragma unroll
            for (int q = 0; q < 4; q++) acc[i][j][q] = 0.0f;

    const int mBase = (wid & 1) * 64;
    const int nBase = (wid >> 1) * 32;
    uint32_t aoff[4], boff4[2];
    #pragma unroll
    for (int mi = 0; mi < 4; mi++) {
        int r = mBase + mi*16 + (lane & 15);
        int kk = (lane >> 4) * 8;
        aoff[mi] = (uint32_t)((r*PAD + kk) * 2);
    }
    #pragma unroll
    for (int nj = 0; nj < 2; nj++) {
        int r = nBase + nj*16 + (lane & 7) + ((lane >> 4) << 3);
        int kk = ((lane >> 3) & 1) * 8;
        boff4[nj] = (uint32_t)((r*PAD + kk) * 2);
    }

    #define PREFETCH(st) do {                                                  \
        const int k0_ = (st) * 32;                                             \
        uint32_t ab = aB[(st) % 3], bb = bB[(st) % 3];                         \
        _Pragma("unroll")                                                      \
        for (int j = 0; j < 2; j++) {                                          \
            asm volatile("cp.async.ca.shared.global [%0], [%1], 16, %2;"       \
                :: "r"(ab + dstA[j]), "l"(srcA[j] + k0_), "r"(szA[j]));        \
            asm volatile("cp.async.ca.shared.global [%0], [%1], 16;"           \
                :: "r"(bb + dstA[j]), "l"(srcB[j] + k0_));                     \
        }                                                                      \
        asm volatile("cp.async.commit_group;");                                \
    } while (0)

    PREFETCH(0);
    PREFETCH(1);

    for (int s = 0; s < NST; s++) {
        asm volatile("cp.async.wait_group 1;");
        __syncthreads();
        if (s + 2 < NST) PREFETCH(s + 2);
        else asm volatile("cp.async.commit_group;");
        uint32_t ab = aB[s % 3], bb = bB[s % 3];
        #pragma unroll
        for (int ks = 0; ks < 2; ks++) {
            uint32_t a[4][4], b[4][2];
            #pragma unroll
            for (int mi = 0; mi < 4; mi++)
                asm volatile("ldmatrix.sync.aligned.m8n8.x4.shared.b16 {%0,%1,%2,%3}, [%4];"
                    : "=r"(a[mi][0]), "=r"(a[mi][1]), "=r"(a[mi][2]), "=r"(a[mi][3])
                    : "r"(ab + aoff[mi] + ks*32));
            #pragma unroll
            for (int nj = 0; nj < 2; nj++)
                asm volatile("ldmatrix.sync.aligned.m8n8.x4.shared.b16 {%0,%1,%2,%3}, [%4];"
                    : "=r"(b[2*nj][0]), "=r"(b[2*nj][1]),
                      "=r"(b[2*nj+1][0]), "=r"(b[2*nj+1][1])
                    : "r"(bb + boff4[nj] + ks*32));
            #pragma unroll
            for (int mi = 0; mi < 4; mi++)
                #pragma unroll
                for (int ni = 0; ni < 4; ni++)
                    asm volatile(
                        "mma.sync.aligned.m16n8k16.row.col.f32.f16.f16.f32 "
                        "{%0,%1,%2,%3}, {%4,%5,%6,%7}, {%8,%9}, {%0,%1,%2,%3};"
                        : "+f"(acc[mi][ni][0]), "+f"(acc[mi][ni][1]),
                          "+f"(acc[mi][ni][2]), "+f"(acc[mi][ni][3])
                        : "r"(a[mi][0]), "r"(a[mi][1]), "r"(a[mi][2]), "r"(a[mi][3]),
                          "r"(b[ni][0]), "r"(b[ni][1]));
        }
    }

    const int qrow = lane >> 2, qcol = (lane & 3) * 2;

    if (MODE == 0) {
        __syncthreads();   // all warps done reading dsm before reuse as sg
        float* sg = (float*)dsm;   // 128 x 64 fp32 = 32 KB
        if (wid < 4) {
            #pragma unroll
            for (int mi = 0; mi < 4; mi++) {
                int r0 = mBase + mi*16 + qrow;
                #pragma unroll
                for (int ni = 0; ni < 4; ni++) {
                    int c = nBase + ni*8 + qcol;
                    sg[r0*64 + c]     = acc[mi][ni][0];
                    sg[r0*64 + c + 1] = acc[mi][ni][1];
                    sg[(r0+8)*64 + c]     = acc[mi][ni][2];
                    sg[(r0+8)*64 + c + 1] = acc[mi][ni][3];
                }
            }
        }
        __syncthreads();
        if (wid >= 4) {
            #pragma unroll
            for (int mi = 0; mi < 4; mi++) {
                int r0 = mBase + mi*16 + qrow;
                int a0 = s_arow[r0], a1 = s_arow[r0 + 8];
                #pragma unroll
                for (int ni = 0; ni < 4; ni++) {
                    int c = (nBase - 64) + ni*8 + qcol;
                    if (a0 >= 0) {
                        float gA = sg[r0*64 + c], gB = sg[r0*64 + c + 1];
                        float vA = (gA / (1.0f + expf(-gA))) * acc[mi][ni][0];
                        float vB = (gB / (1.0f + expf(-gB))) * acc[mi][ni][1];
                        *(__half2*)&g_i[(size_t)a0*INTER + y*64 + c] = __floats2half2_rn(vA, vB);
                    }
                    if (a1 >= 0) {
                        float gA = sg[(r0+8)*64 + c], gB = sg[(r0+8)*64 + c + 1];
                        float vA = (gA / (1.0f + expf(-gA))) * acc[mi][ni][2];
                        float vB = (gB / (1.0f + expf(-gB))) * acc[mi][ni][3];
                        *(__half2*)&g_i[(size_t)a1*INTER + y*64 + c] = __floats2half2_rn(vA, vB);
                    }
                }
            }
        }
    } else {
        #pragma unroll
        for (int mi = 0; mi < 4; mi++) {
            int r0 = mBase + mi*16 + qrow;
            int a0 = s_arow[r0], a1 = s_arow[r0 + 8];
            float w0 = 0.f, w1 = 0.f;
            float *O0 = nullptr, *O1 = nullptr;
            if (a0 >= 0) { w0 = topw[a0]; O0 = out + (size_t)(a0 >> 1)*HIDDEN + n0; }
            if (a1 >= 0) { w1 = topw[a1]; O1 = out + (size_t)(a1 >> 1)*HIDDEN + n0; }
            #pragma unroll
            for (int ni = 0; ni < 4; ni++) {
                int c = nBase + ni*8 + qcol;
                if (O0) {
                    atomicAdd(&O0[c],     w0 * acc[mi][ni][0]);
                    atomicAdd(&O0[c + 1], w0 * acc[mi][ni][1]);
                }
                if (O1) {
                    atomicAdd(&O1[c],     w1 * acc[mi][ni][2]);
                    atomicAdd(&O1[c + 1], w1 * acc[mi][ni][3]);
                }
            }
        }
    }
}

// ---------------- launch ----------------
extern "C" void kernel_launch(void* const* d_in, const int* in_sizes, int n_in,
                              void* d_out, int out_size) {
    const float* hidden  = (const float*)d_in[0];
    const int*   topk    = (const int*)  d_in[1];
    const float* topw    = (const float*)d_in[2];
    const float* gup_w   = (const float*)d_in[3];
    const float* dwn_w   = (const float*)d_in[4];
    const int*   gup_p   = (const int*)  d_in[5];
    const float* gup_a   = (const float*)d_in[6];
    const int*   dwn_p   = (const int*)  d_in[7];
    const float* dwn_a   = (const float*)d_in[8];
    const float* gup_ch  = (const float*)d_in[9];
    const float* dwn_ch  = (const float*)d_in[10];
    float* out = (float*)d_out;

    static int s_attr_done = 0;
    if (!s_attr_done) {
        cudaFuncSetAttribute(k_gemm<HIDDEN,0>, cudaFuncAttributeMaxDynamicSharedMemorySize, GEMM_DSMEM);
        cudaFuncSetAttribute(k_gemm<INTER, 1>, cudaFuncAttributeMaxDynamicSharedMemorySize, GEMM_DSMEM);
        s_attr_done = 1;
    }

    k_trig<<<(NROT*HIDDEN/2 + 255)/256, 256>>>(gup_a, dwn_a);                     // 1
    k_prep<HIDDEN, true ><<<(NE*O2/2)*16/8,   256>>>(gup_w, gup_p, gup_ch);       // 2
    k_hrot<<<(TOKENS/2)*16/8, 256>>>(hidden, gup_p, gup_ch, topk, out);           // 3
    k_gemm<HIDDEN, 0><<<dim3(NE*TPE, INTER/64), 256, GEMM_DSMEM>>>(topw, out);    // 4 (profiled)
    k_prep<INTER,  false><<<(NE*HIDDEN/2)*6/8, 256>>>(dwn_w, dwn_p, dwn_ch);      // 5
    k_irot<<<(NASSIGN/2)*6/8, 256>>>(dwn_p, dwn_ch);                              // 6
    k_gemm<INTER,  1><<<dim3(NE*TPE, HIDDEN/128), 256, GEMM_DSMEM>>>(topw, out);  // 7
}